// round 6
// baseline (speedup 1.0000x reference)
#include <cuda_runtime.h>
#include <cuda_fp16.h>
#include <cstdint>

#define BB 8
#define CC 64
#define NN 4096
#define CI 8

// ---------------- scratch (no allocation allowed) ----------------
__device__ __align__(16) __half g_qh[BB * NN * CI];     // [b][n][8]
__device__ __align__(16) __half g_kh[BB * NN * CI];     // [b][m][8], pre-scaled log2e/sqrt(8)
__device__ __align__(16) __half g_vt[BB * CI * NN];     // [b][i][n]  (V transposed)
__device__ __align__(16) float  g_pA[4 * BB * NN * CI]; // [q][b][m][8] partial P@V
__device__ __align__(16) float  g_pD[4 * BB * NN];      // [q][b][m]   partial denom
__device__ int g_cnt[BB * 64];                          // split-K arrival counters (self-reset)

// ---------------- mma helpers (baseline sm_80+ features only) --------------
// S-MMA: f16 in, f16 out. D = {row gid cols 2cp..+1, row gid+8 cols 2cp..+1}
__device__ __forceinline__ void mma_s_f16(uint32_t& d0, uint32_t& d1,
                                          uint32_t a0, uint32_t a1, uint32_t b0) {
    asm("mma.sync.aligned.m16n8k8.row.col.f16.f16.f16.f16 "
        "{%0,%1}, {%2,%3}, {%4}, {%5,%6};"
        : "=r"(d0), "=r"(d1)
        : "r"(a0), "r"(a1), "r"(b0), "r"(0u), "r"(0u));
}
// PV-MMA: f16 accum (2 regs)
__device__ __forceinline__ void mma_pv_f16(uint32_t& c0, uint32_t& c1,
                                           uint32_t a0, uint32_t a1, uint32_t a2, uint32_t a3,
                                           uint32_t b0, uint32_t b1) {
    asm("mma.sync.aligned.m16n8k16.row.col.f16.f16.f16.f16 "
        "{%0,%1}, {%2,%3,%4,%5}, {%6,%7}, {%0,%1};"
        : "+r"(c0), "+r"(c1)
        : "r"(a0), "r"(a1), "r"(a2), "r"(a3), "r"(b0), "r"(b1));
}
// den-MMA: f32 accum
__device__ __forceinline__ void mma_m16n8k16_f32(float& c0, float& c1, float& c2, float& c3,
                                                 uint32_t a0, uint32_t a1, uint32_t a2, uint32_t a3,
                                                 uint32_t b0, uint32_t b1) {
    asm("mma.sync.aligned.m16n8k16.row.col.f32.f16.f16.f32 "
        "{%0,%1,%2,%3}, {%4,%5,%6,%7}, {%8,%9}, {%0,%1,%2,%3};"
        : "+f"(c0), "+f"(c1), "+f"(c2), "+f"(c3)
        : "r"(a0), "r"(a1), "r"(a2), "r"(a3), "r"(b0), "r"(b1));
}
__device__ __forceinline__ uint32_t ex2_h2(uint32_t x) {
    uint32_t r;
    asm("ex2.approx.f16x2 %0, %1;" : "=r"(r) : "r"(x));
    return r;
}
__device__ __forceinline__ uint32_t hadd2u(uint32_t a, uint32_t b) {
    __half2 r = __hadd2(*reinterpret_cast<__half2*>(&a), *reinterpret_cast<__half2*>(&b));
    return *reinterpret_cast<uint32_t*>(&r);
}
__device__ __forceinline__ float2 h2f2(uint32_t a) {
    return __half22float2(*reinterpret_cast<__half2*>(&a));
}

// ---------------- kernel 1: q/k/v projections (4-way c-split) --------------
__global__ void __launch_bounds__(256) proj_kernel(const float* __restrict__ x,
                                                   const float* __restrict__ Wq,
                                                   const float* __restrict__ Wk,
                                                   const float* __restrict__ Wv) {
    __shared__ float swq[CI * CC], swk[CI * CC], swv[CI * CC];
    __shared__ __half sv[CI][64];
    int tid = threadIdx.x;
    for (int i = tid; i < CI * CC; i += 256) {
        swq[i] = Wq[i]; swk[i] = Wk[i]; swv[i] = Wv[i];
    }
    __syncthreads();

    int wid = tid >> 5, lane = tid & 31;
    int quarter = lane >> 3, nl = lane & 7;
    int slot = blockIdx.x * 64 + wid * 8 + nl;     // grid 512 -> 32768 slots
    int b = slot >> 12, n = slot & (NN - 1);
    int nloc = (wid << 3) | nl;

    float q[CI], k[CI], v[CI];
#pragma unroll
    for (int i = 0; i < CI; i++) { q[i] = 0.f; k[i] = 0.f; v[i] = 0.f; }

    const float* xp = x + (size_t)b * CC * NN + n;
    int c0 = quarter * 16;
#pragma unroll
    for (int j = 0; j < 16; j++) {
        int c = c0 + j;
        float xv = xp[(size_t)c * NN];
#pragma unroll
        for (int i = 0; i < CI; i++) {
            q[i] = fmaf(swq[i * CC + c], xv, q[i]);
            k[i] = fmaf(swk[i * CC + c], xv, k[i]);
            v[i] = fmaf(swv[i * CC + c], xv, v[i]);
        }
    }
#pragma unroll
    for (int i = 0; i < CI; i++) {
        q[i] += __shfl_xor_sync(0xffffffffu, q[i], 8);
        k[i] += __shfl_xor_sync(0xffffffffu, k[i], 8);
        v[i] += __shfl_xor_sync(0xffffffffu, v[i], 8);
        q[i] += __shfl_xor_sync(0xffffffffu, q[i], 16);
        k[i] += __shfl_xor_sync(0xffffffffu, k[i], 16);
        v[i] += __shfl_xor_sync(0xffffffffu, v[i], 16);
    }
    if (quarter == 0) {
        const float KS = 0.51006971f;  // log2(e)/sqrt(8)
        size_t base = ((size_t)b * NN + n) * CI;
        __half2 qh[4], kh[4];
#pragma unroll
        for (int i = 0; i < 4; i++) {
            qh[i] = __floats2half2_rn(q[2 * i], q[2 * i + 1]);
            kh[i] = __floats2half2_rn(k[2 * i] * KS, k[2 * i + 1] * KS);
        }
        *reinterpret_cast<uint4*>(&g_qh[base]) = *reinterpret_cast<uint4*>(qh);
        *reinterpret_cast<uint4*>(&g_kh[base]) = *reinterpret_cast<uint4*>(kh);
#pragma unroll
        for (int i = 0; i < CI; i++) sv[i][nloc] = __float2half_rn(v[i]);
    }
    __syncthreads();
    if (tid < 64) {
        int row = tid >> 3, chunk = tid & 7;
        int nbase = (blockIdx.x & 63) * 64;
        int bb = blockIdx.x >> 6;
        *reinterpret_cast<uint4*>(g_vt + ((size_t)bb * CI + row) * NN + nbase + chunk * 8) =
            *reinterpret_cast<const uint4*>(&sv[row][chunk * 8]);
    }
}

// ---------------- kernel 2: FA2 attention, f16-accum + split-K(4) ----------
// grid 2048: b = bx>>8, mt = (bx>>2)&63, quarter = bx&3. 128 threads = 4 warps.
#define VPAD 264

__global__ void __launch_bounds__(128) attn_kernel(const float* __restrict__ x,
                                                   const float* __restrict__ Wout,
                                                   float* __restrict__ out) {
    __shared__ __align__(16) uint4 sQ[256];          // Q tile [256][8] halves
    __shared__ __align__(16) __half sV[CI * VPAD];   // Vt tile [8][256] padded
    __shared__ float sAtt[64 * 9];
    __shared__ float sW[CC * CI];
    __shared__ int s_old;

    int tid = threadIdx.x, wid = tid >> 5, lane = tid & 31;
    int gid = lane >> 2, cp = lane & 3;
    int b = blockIdx.x >> 8, mt = (blockIdx.x >> 2) & 63, quarter = blockIdx.x & 3;
    int m0 = mt * 64;
    int nbase = quarter * 1024;

    int mrow = m0 + wid * 16 + gid;
    uint32_t ka0 = *reinterpret_cast<const uint32_t*>(
        &g_kh[((size_t)b * NN + mrow) * CI + 2 * cp]);
    uint32_t ka1 = *reinterpret_cast<const uint32_t*>(
        &g_kh[((size_t)b * NN + mrow + 8) * CI + 2 * cp]);

    const uint4* qbase = reinterpret_cast<const uint4*>(g_qh + (size_t)b * NN * CI);
    const __half* vbase = g_vt + (size_t)b * CI * NN;

    // f16 PV accumulators, even/odd chunk streams (2 regs each)
    uint32_t aE0 = 0, aE1 = 0, aO0 = 0, aO1 = 0;
    float den0 = 0.f, den1 = 0.f, den2 = 0.f, den3 = 0.f;
    const uint32_t ONES = 0x3C003C00u;

    int r0 = tid >> 5, c0i = tid & 31;
    int r1 = (tid + 128) >> 5;

    uint4 q4a = qbase[nbase + tid];
    uint4 q4b = qbase[nbase + tid + 128];
    uint4 v4a = *reinterpret_cast<const uint4*>(vbase + (size_t)r0 * NN + nbase + c0i * 8);
    uint4 v4b = *reinterpret_cast<const uint4*>(vbase + (size_t)r1 * NN + nbase + c0i * 8);

    const uint32_t* sQw = reinterpret_cast<const uint32_t*>(sQ);
    const uint32_t* qp = sQw + gid * 4 + cp;
    const __half* vp = sV + gid * VPAD + 2 * cp;

    for (int bi = 0; bi < 4; bi++) {
        sQ[tid] = q4a;
        sQ[tid + 128] = q4b;
        *reinterpret_cast<uint4*>(&sV[r0 * VPAD + c0i * 8]) = v4a;
        *reinterpret_cast<uint4*>(&sV[r1 * VPAD + c0i * 8]) = v4b;
        __syncthreads();

        if (bi < 3) {
            int n1 = nbase + (bi + 1) * 256;
            q4a = qbase[n1 + tid];
            q4b = qbase[n1 + tid + 128];
            v4a = *reinterpret_cast<const uint4*>(vbase + (size_t)r0 * NN + n1 + c0i * 8);
            v4b = *reinterpret_cast<const uint4*>(vbase + (size_t)r1 * NN + n1 + c0i * 8);
        }

        // 4 groups of 64 n; inside each group: 4 chunks of 16 n
#pragma unroll
        for (int g = 0; g < 4; g++) {
            int no = g * 64;
            uint32_t P[4][4];
#pragma unroll
            for (int c = 0; c < 4; c++) {
                int nc = no + c * 16;
                uint32_t qL = qp[nc * 4];
                uint32_t qH = qp[(nc + 8) * 4];
                uint32_t s01, s23, s45, s67;
                mma_s_f16(s01, s23, ka0, ka1, qL);
                mma_s_f16(s45, s67, ka0, ka1, qH);
                P[c][0] = ex2_h2(s01);
                P[c][1] = ex2_h2(s23);
                P[c][2] = ex2_h2(s45);
                P[c][3] = ex2_h2(s67);
            }
#pragma unroll
            for (int c = 0; c < 4; c++) {
                int nc = no + c * 16;
                uint32_t vb0 = *reinterpret_cast<const uint32_t*>(vp + nc);
                uint32_t vb1 = *reinterpret_cast<const uint32_t*>(vp + nc + 8);
                if (c & 1)
                    mma_pv_f16(aO0, aO1, P[c][0], P[c][1], P[c][2], P[c][3], vb0, vb1);
                else
                    mma_pv_f16(aE0, aE1, P[c][0], P[c][1], P[c][2], P[c][3], vb0, vb1);
            }
            // denominator: sum 4 chunks' P elementwise (exact in f16 range), one f32 MMA
            uint32_t t0 = hadd2u(hadd2u(P[0][0], P[1][0]), hadd2u(P[2][0], P[3][0]));
            uint32_t t1 = hadd2u(hadd2u(P[0][1], P[1][1]), hadd2u(P[2][1], P[3][1]));
            uint32_t t2 = hadd2u(hadd2u(P[0][2], P[1][2]), hadd2u(P[2][2], P[3][2]));
            uint32_t t3 = hadd2u(hadd2u(P[0][3], P[1][3]), hadd2u(P[2][3], P[3][3]));
            mma_m16n8k16_f32(den0, den1, den2, den3, t0, t1, t2, t3, ONES, ONES);
        }
        __syncthreads();
    }

    // combine E/O f16 accumulators in f32
    float2 e0 = h2f2(aE0), e1 = h2f2(aE1), o0 = h2f2(aO0), o1 = h2f2(aO1);
    float acc0 = e0.x + o0.x, acc1 = e0.y + o0.y;   // row gid,   cols 2cp, 2cp+1
    float acc2 = e1.x + o1.x, acc3 = e1.y + o1.y;   // row gid+8

    {
        size_t rb = ((size_t)quarter * BB + b) * NN;
        *reinterpret_cast<float2*>(&g_pA[(rb + mrow) * CI + 2 * cp]) = make_float2(acc0, acc1);
        *reinterpret_cast<float2*>(&g_pA[(rb + mrow + 8) * CI + 2 * cp]) = make_float2(acc2, acc3);
        if (cp == 0) {
            g_pD[rb + mrow] = den0;
            g_pD[rb + mrow + 8] = den2;
        }
    }
    __threadfence();
    __syncthreads();
    if (tid == 0) s_old = atomicAdd(&g_cnt[b * 64 + mt], 1);
    __syncthreads();
    if (s_old != 3) return;                // first three exit; last merges + epilogue
    if (tid == 0) g_cnt[b * 64 + mt] = 0;  // reset for next (graph-replayed) launch
    __threadfence();

    for (int i = tid; i < CC * CI; i += 128) sW[i] = Wout[i];
    if (tid < 64) {
        int m = m0 + tid;
        float acc[CI] = {0, 0, 0, 0, 0, 0, 0, 0};
        float den = 0.f;
#pragma unroll
        for (int qq = 0; qq < 4; qq++) {
            size_t rb = ((size_t)qq * BB + b) * NN + m;
            const float4* a = reinterpret_cast<const float4*>(&g_pA[rb * CI]);
            float4 x0 = a[0], x1 = a[1];
            acc[0] += x0.x; acc[1] += x0.y; acc[2] += x0.z; acc[3] += x0.w;
            acc[4] += x1.x; acc[5] += x1.y; acc[6] += x1.z; acc[7] += x1.w;
            den += g_pD[rb];
        }
        float inv = 1.0f / den;
#pragma unroll
        for (int i = 0; i < CI; i++) sAtt[tid * 9 + i] = acc[i] * inv;
    }
    __syncthreads();

    // epilogue: out = x + 0.1 * Wout @ att
    int ml = tid & 63, chalf = tid >> 6;
    float att[CI];
#pragma unroll
    for (int i = 0; i < CI; i++) att[i] = sAtt[ml * 9 + i];

    int m = m0 + ml;
    const float* xp = x + (size_t)b * CC * NN + m;
    float* op = out + (size_t)b * CC * NN + m;
#pragma unroll 8
    for (int j = 0; j < 32; j++) {
        int c = chalf * 32 + j;
        float o = 0.f;
#pragma unroll
        for (int i = 0; i < CI; i++) o = fmaf(sW[c * CI + i], att[i], o);
        op[(size_t)c * NN] = fmaf(0.1f, o, xp[(size_t)c * NN]);
    }
}

// ---------------- launch ----------------
extern "C" void kernel_launch(void* const* d_in, const int* in_sizes, int n_in,
                              void* d_out, int out_size) {
    const float* x = (const float*)d_in[0];
    const float* Wq = (const float*)d_in[1];
    const float* Wk = (const float*)d_in[2];
    const float* Wv = (const float*)d_in[3];
    const float* Wout = (const float*)d_in[4];
    float* out = (float*)d_out;

    proj_kernel<<<512, 256>>>(x, Wq, Wk, Wv);
    attn_kernel<<<2048, 128>>>(x, Wout, out);
}